// round 2
// baseline (speedup 1.0000x reference)
#include <cuda_runtime.h>
#include <cuda_bf16.h>

#define NSAMP 128

__global__ __launch_bounds__(NSAMP) void surf_kernel(
    const int2*   __restrict__ x,       // [B, N] pairs of int32 grid indices
    const float*  __restrict__ dvec,    // [B, 16]
    const float4* __restrict__ grid,    // [TABLE] float4 (FEAT=4)
    const float*  __restrict__ W0,      // [22, 8] row-major
    const float*  __restrict__ W1,      // [8, 3]  row-major
    float*        __restrict__ out_sigma, // [B, N]
    float*        __restrict__ out_rgb)   // [B, 3]
{
    const int b    = blockIdx.x;
    const int n    = threadIdx.x;
    const int lane = n & 31;
    const int wid  = n >> 5;

    // ---- issue the long-latency gathers FIRST (DRAM latency shadow) ----
    const int2 idx = __ldg(&x[(long)b * NSAMP + n]);
    const float4 f0 = __ldg(&grid[idx.x]);
    const float4 f1 = __ldg(&grid[idx.y]);

    __shared__ float sW0g[6][8];   // W0 rows 16..21 (geo-feat part)
    __shared__ float sW1[8][3];
    __shared__ float sBase[8];     // per-ray d @ W0[0:16]
    __shared__ float sD[16];
    __shared__ float sWarpProd[4];
    __shared__ float sRGB[4][3];

    // ---- cooperative constant loads (runs under gather shadow) ----
    if (n < 48) {
        int r = n >> 3, c = n & 7;
        sW0g[r][c] = W0[(16 + r) * 8 + c];
    } else if (n < 72) {
        int t = n - 48;
        sW1[t / 3][t % 3] = W1[t];
    } else if (n < 88) {
        sD[n - 72] = dvec[b * 16 + (n - 72)];
    }
    __syncthreads();

    // per-ray hidden-layer bias from view direction (amortized over 128 samples)
    if (n < 8) {
        float acc = 0.f;
        #pragma unroll
        for (int i = 0; i < 16; i++) acc = fmaf(sD[i], W0[i * 8 + n], acc);
        sBase[n] = acc;
    }

    const float sigma = 1.0f / (1.0f + __expf(-(f0.x * f1.x)));
    out_sigma[(long)b * NSAMP + n] = sigma;

    __syncthreads();   // sBase ready

    // ---- tiny MLP: geo part only (6 -> 8 relu -> 3 sigmoid) ----
    float h[8];
    #pragma unroll
    for (int j = 0; j < 8; j++) {
        float v = sBase[j];
        v = fmaf(f0.y, sW0g[0][j], v);
        v = fmaf(f0.z, sW0g[1][j], v);
        v = fmaf(f0.w, sW0g[2][j], v);
        v = fmaf(f1.y, sW0g[3][j], v);
        v = fmaf(f1.z, sW0g[4][j], v);
        v = fmaf(f1.w, sW0g[5][j], v);
        h[j] = fmaxf(v, 0.f);
    }
    float col[3];
    #pragma unroll
    for (int c = 0; c < 3; c++) {
        float v = 0.f;
        #pragma unroll
        for (int j = 0; j < 8; j++) v = fmaf(h[j], sW1[j][c], v);
        col[c] = 1.0f / (1.0f + __expf(-v));
    }

    // ---- exclusive product-scan for transmittance T ----
    float sp = 1.0f - sigma;
    #pragma unroll
    for (int o = 1; o < 32; o <<= 1) {
        float v = __shfl_up_sync(0xffffffffu, sp, o);
        if (lane >= o) sp *= v;
    }
    if (lane == 31) sWarpProd[wid] = sp;
    __syncthreads();
    float prefix = 1.0f;
    #pragma unroll
    for (int w = 0; w < 4; w++) if (w < wid) prefix *= sWarpProd[w];
    float excl = __shfl_up_sync(0xffffffffu, sp, 1);
    if (lane == 0) excl = 1.0f;
    const float T = prefix * excl;
    const float wgt = T * sigma;

    // ---- rgb = sum_n wgt * color ----
    float r0 = wgt * col[0], r1 = wgt * col[1], r2 = wgt * col[2];
    #pragma unroll
    for (int o = 16; o > 0; o >>= 1) {
        r0 += __shfl_down_sync(0xffffffffu, r0, o);
        r1 += __shfl_down_sync(0xffffffffu, r1, o);
        r2 += __shfl_down_sync(0xffffffffu, r2, o);
    }
    if (lane == 0) { sRGB[wid][0] = r0; sRGB[wid][1] = r1; sRGB[wid][2] = r2; }
    __syncthreads();
    if (n < 3) {
        out_rgb[b * 3 + n] = sRGB[0][n] + sRGB[1][n] + sRGB[2][n] + sRGB[3][n];
    }
}

extern "C" void kernel_launch(void* const* d_in, const int* in_sizes, int n_in,
                              void* d_out, int out_size) {
    const int2*   x    = (const int2*)d_in[0];
    const float*  dvec = (const float*)d_in[1];
    const float4* grid = (const float4*)d_in[2];
    const float*  W0   = (const float*)d_in[3];
    const float*  W1   = (const float*)d_in[4];

    const int B = in_sizes[1] / 16;          // d is [B, 16]
    float* out_sigma = (float*)d_out;        // [B, 128]
    float* out_rgb   = out_sigma + (long)B * NSAMP;  // [B, 3]

    surf_kernel<<<B, NSAMP>>>(x, dvec, grid, W0, W1, out_sigma, out_rgb);
}